// round 14
// baseline (speedup 1.0000x reference)
#include <cuda_runtime.h>
#include <math.h>
#include <stdint.h>

// ---------------- problem constants ----------------
#define FH 200
#define FW 272
#define HWP (FH*FW)          // 54400 pixels
#define CIN 256
#define NA (HWP*9)           // 489600 anchors
#define PRE_NMS 6000
#define POST_NMS 1000
#define MWORDS 94            // ceil(6000/64)

// ---------------- device scratch (static, no allocs) ----------------
__device__ float g_x[CIN*HWP];                    // conv1 output (relu'd), NCHW
__device__ float g_wB[4*32*72*64];                // weights [cob][chunk][ci*9+k][co64], contiguous per (cob,chunk)
__device__ float g_conf[NA];
__device__ float g_offs[NA*4];
__device__ int   g_idxGT[PRE_NMS];
__device__ int   g_idxEQ[NA];
__device__ int   g_cand[PRE_NMS];
__device__ int   g_sortedIdx[PRE_NMS];
__device__ float4 g_boxes[PRE_NMS];
__device__ unsigned char g_valid[PRE_NMS];
__device__ unsigned long long g_sup[(size_t)PRE_NMS*MWORDS + 1024];

__device__ unsigned g_hist[256];
__device__ unsigned g_prefix, g_maskv, g_thresh;
__device__ int g_k, g_cntGT, g_cntEQ;

// ---------------- helpers ----------------
__device__ __forceinline__ unsigned ordf(float f) {
    unsigned u = __float_as_uint(f);
    return (u & 0x80000000u) ? ~u : (u | 0x80000000u);   // monotonic increasing map
}
__device__ __forceinline__ unsigned long long fma2(unsigned long long a,
                                                   unsigned long long b,
                                                   unsigned long long c) {
    unsigned long long d;
    asm("fma.rn.f32x2 %0, %1, %2, %3;" : "=l"(d) : "l"(a), "l"(b), "l"(c));
    return d;
}
__device__ __forceinline__ unsigned long long pack2(float x, float y) {
    unsigned long long r;
    asm("mov.b64 %0, {%1, %2};" : "=l"(r) : "f"(x), "f"(y));
    return r;
}
__device__ __forceinline__ float2 unpack2(unsigned long long v) {
    float2 r;
    asm("mov.b64 {%0, %1}, %2;" : "=f"(r.x), "=f"(r.y) : "l"(v));
    return r;
}
__device__ __forceinline__ void mbar_init(uint32_t addr, uint32_t cnt) {
    asm volatile("mbarrier.init.shared.b64 [%0], %1;" :: "r"(addr), "r"(cnt) : "memory");
}
__device__ __forceinline__ void mbar_expect(uint32_t addr, uint32_t bytes) {
    asm volatile("mbarrier.arrive.expect_tx.shared.b64 _, [%0], %1;"
                 :: "r"(addr), "r"(bytes) : "memory");
}
__device__ __forceinline__ void mbar_wait(uint32_t addr, uint32_t parity) {
    asm volatile(
        "{\n\t.reg .pred P;\n\t"
        "WL_%=:\n\t"
        "mbarrier.try_wait.parity.acquire.cta.shared::cta.b64 P, [%0], %1, 0x989680;\n\t"
        "@P bra.uni WD_%=;\n\t"
        "bra.uni WL_%=;\n\t"
        "WD_%=:\n\t}"
        :: "r"(addr), "r"(parity) : "memory");
}
__device__ __forceinline__ void cpbulk(uint32_t dst, const void* src, uint32_t size, uint32_t bar) {
    asm volatile("cp.async.bulk.shared::cta.global.mbarrier::complete_tx::bytes [%0], [%1], %2, [%3];"
                 :: "r"(dst), "l"(src), "r"(size), "r"(bar) : "memory");
}

// ---------------- init ----------------
__global__ void init_kernel(float* out, int out_n) {
    int t = blockIdx.x * blockDim.x + threadIdx.x;
    for (int i = t; i < out_n; i += gridDim.x * blockDim.x) out[i] = 0.f;
    if (blockIdx.x == 0) {
        if (threadIdx.x < 256) g_hist[threadIdx.x] = 0;
        if (threadIdx.x == 0) {
            g_prefix = 0; g_maskv = 0; g_k = PRE_NMS;
            g_cntGT = 0; g_cntEQ = 0;
        }
    }
}

// ---------------- weight transpose: w1[co][ci][k] -> wB[cob][chunk][cil*9+k][col] ----------------
__global__ void wtrans_kernel(const float* __restrict__ w1) {
    int t = blockIdx.x * blockDim.x + threadIdx.x;
    if (t >= CIN * CIN * 9) return;
    int co = t & 255;
    int rem = t >> 8;          // ci*9 + k
    int k = rem % 9;
    int ci = rem / 9;
    int cob = co >> 6, col = co & 63;
    int c = ci >> 3, cil = ci & 7;
    g_wB[((((size_t)cob * 32 + c) * 72) + cil * 9 + k) * 64 + col] =
        w1[(co * CIN + ci) * 9 + k];
}

// ---------------- conv 3x3 + relu (co-paired f32x2, cp.async.bulk double-buffered) ----------------
// tile 8x16 px, 64 couts, 128 threads, 8 px x 4 co-pairs/thread (R9 math, bulk staging).
// smem floats: sW[2][4608] at 0, sIn[2][80*24] at 9216; mbarriers at byte 52224.
#define W_ELEMS 4608
#define IN_ELEMS 1920
#define IN_OFF (2*W_ELEMS)
#define BAR_OFFB ((2*W_ELEMS + 2*IN_ELEMS) * 4)
#define SM_TOTALB (BAR_OFFB + 64)
__global__ void __launch_bounds__(128, 3) conv3x3_kernel(const float* __restrict__ f,
                                                         const float* __restrict__ b1) {
    extern __shared__ float sm[];
    uint32_t sbase;
    asm("{ .reg .u64 t; cvta.to.shared.u64 t, %1; cvt.u32.u64 %0, t; }"
        : "=r"(sbase) : "l"(sm));

    const int tid = threadIdx.x;
    const int cot = tid & 7;           // co-pair group: pairs cot + 8*o, o=0..3
    const int pt  = tid >> 3;          // 0..15 pixel groups
    const int pr  = pt >> 1;           // row 0..7
    const int pc  = (pt & 1) << 3;     // col base 0 or 8
    const int tileC = blockIdx.x * 16;
    const int tileR = blockIdx.y * 8;

    const bool leftE  = (blockIdx.x == 0);
    const bool rightE = ((int)blockIdx.x == FW / 16 - 1);
    const int  srccol = leftE ? 0 : (tileC - 4);
    const int  dstoffB = leftE ? 16 : 0;
    const uint32_t rowszB = (leftE || rightE) ? 80u : 96u;
    const int  nvr = 10 - (blockIdx.y == 0 ? 1 : 0)
                        - ((int)blockIdx.y == FH / 8 - 1 ? 1 : 0);
    const uint32_t ibytes = 8u * (uint32_t)nvr * rowszB;

    // zero halos (OOB rows, edge columns) in both buffers — one-time
    for (int e = tid; e < 2 * IN_ELEMS; e += 128) {
        int bb = e / IN_ELEMS, idx = e - bb * IN_ELEMS;
        int row = idx / 24, col = idx - row * 24;
        int rr = row % 10;
        int gr = tileR + rr - 1;
        bool z = (gr < 0) || (gr >= FH) || (leftE && col < 4) || (rightE && col >= 20);
        if (z) sm[IN_OFF + bb * IN_ELEMS + idx] = 0.f;
    }
    if (tid == 0) {
        mbar_init(sbase + BAR_OFFB, 1);
        mbar_init(sbase + BAR_OFFB + 8, 1);
    }
    __syncthreads();

    auto stage = [&](int c, int b) {   // tid 0 only
        uint32_t bar = sbase + BAR_OFFB + b * 8;
        mbar_expect(bar, 18432u + ibytes);
        cpbulk(sbase + (uint32_t)(b * W_ELEMS) * 4,
               g_wB + (((size_t)blockIdx.z * 32 + c) * 72) * 64, 18432u, bar);
        int ci0 = c * 8;
#pragma unroll 1
        for (int ci = 0; ci < 8; ci++) {
            const float* srow = f + (size_t)(ci0 + ci) * HWP + srccol;
            uint32_t drow = sbase + (uint32_t)(IN_OFF + b * IN_ELEMS) * 4
                          + (uint32_t)(ci * 10) * 96 + dstoffB;
#pragma unroll 1
            for (int rr = 0; rr < 10; rr++) {
                int gr = tileR + rr - 1;
                if ((unsigned)gr < (unsigned)FH)
                    cpbulk(drow + rr * 96, srow + (size_t)gr * FW, rowszB, bar);
            }
        }
    };

    unsigned long long acc[4][8];      // [co-pair o][pixel j]
#pragma unroll
    for (int o = 0; o < 4; o++)
#pragma unroll
        for (int j = 0; j < 8; j++) acc[o][j] = 0ull;

    if (tid == 0) stage(0, 0);

    for (int c = 0; c < 32; c++) {
        int b = c & 1;
        if (c < 31 && tid == 0) stage(c + 1, b ^ 1);
        mbar_wait(sbase + BAR_OFFB + b * 8, (c >> 1) & 1);

        const float* sW  = sm + b * W_ELEMS;
        const float* sIn = sm + IN_OFF + b * IN_ELEMS;
        for (int ci = 0; ci < 8; ci++) {
#pragma unroll
            for (int dy = 0; dy < 3; dy++) {
                const float* r = sIn + (ci * 10 + pr + dy) * 24 + pc;
                float4 q0 = *(const float4*)r;
                float4 q1 = *(const float4*)(r + 4);
                float4 q2 = *(const float4*)(r + 8);
                float  s12 = r[12];
                unsigned long long X[10];
                X[0] = pack2(q0.w, q0.w);
                X[1] = pack2(q1.x, q1.x); X[2] = pack2(q1.y, q1.y);
                X[3] = pack2(q1.z, q1.z); X[4] = pack2(q1.w, q1.w);
                X[5] = pack2(q2.x, q2.x); X[6] = pack2(q2.y, q2.y);
                X[7] = pack2(q2.z, q2.z); X[8] = pack2(q2.w, q2.w);
                X[9] = pack2(s12, s12);
#pragma unroll
                for (int dx = 0; dx < 3; dx++) {
                    const float* wrow = sW + (ci * 9 + dy * 3 + dx) * 64 + 2 * cot;
#pragma unroll
                    for (int o = 0; o < 4; o++) {
                        unsigned long long w2 = *(const unsigned long long*)&wrow[16 * o];
#pragma unroll
                        for (int j = 0; j < 8; j++)
                            acc[o][j] = fma2(X[j + dx], w2, acc[o][j]);
                    }
                }
            }
        }
        __syncthreads();
    }

    const int gr = tileR + pr;
    const int co0 = blockIdx.z * 64;
#pragma unroll
    for (int o = 0; o < 4; o++) {
        int coe = co0 + 2 * (cot + 8 * o);          // even co of the pair
        float be = b1[coe], bo = b1[coe + 1];
        float2 v[8];
#pragma unroll
        for (int j = 0; j < 8; j++) v[j] = unpack2(acc[o][j]);
        float4 ea, eb, oa, ob;
        ea.x = fmaxf(v[0].x + be, 0.f); ea.y = fmaxf(v[1].x + be, 0.f);
        ea.z = fmaxf(v[2].x + be, 0.f); ea.w = fmaxf(v[3].x + be, 0.f);
        eb.x = fmaxf(v[4].x + be, 0.f); eb.y = fmaxf(v[5].x + be, 0.f);
        eb.z = fmaxf(v[6].x + be, 0.f); eb.w = fmaxf(v[7].x + be, 0.f);
        oa.x = fmaxf(v[0].y + bo, 0.f); oa.y = fmaxf(v[1].y + bo, 0.f);
        oa.z = fmaxf(v[2].y + bo, 0.f); oa.w = fmaxf(v[3].y + bo, 0.f);
        ob.x = fmaxf(v[4].y + bo, 0.f); ob.y = fmaxf(v[5].y + bo, 0.f);
        ob.z = fmaxf(v[6].y + bo, 0.f); ob.w = fmaxf(v[7].y + bo, 0.f);
        float* de = &g_x[(size_t)coe * HWP + gr * FW + tileC + pc];
        float* dd = &g_x[(size_t)(coe + 1) * HWP + gr * FW + tileC + pc];
        *(float4*)de = ea; *(float4*)(de + 4) = eb;
        *(float4*)dd = oa; *(float4*)(dd + 4) = ob;
    }
}

// ---------------- 1x1 heads: conf (9) + offsets (36) ----------------
__global__ void __launch_bounds__(128) heads_kernel(const float* __restrict__ wcls,
                                                    const float* __restrict__ bcls,
                                                    const float* __restrict__ wreg,
                                                    const float* __restrict__ breg) {
    __shared__ float sw[256][48];
    int tid = threadIdx.x;
    for (int idx = tid; idx < 256 * 45; idx += 128) {
        int c = idx / 45, t = idx - c * 45;
        sw[c][t] = (t < 9) ? wcls[t * 256 + c] : wreg[(t - 9) * 256 + c];
    }
    __syncthreads();
    int p = blockIdx.x * 128 + tid;
    if (p >= HWP) return;
    float acc[45];
#pragma unroll
    for (int t = 0; t < 9; t++)  acc[t] = bcls[t];
#pragma unroll
    for (int t = 0; t < 36; t++) acc[9 + t] = breg[t];
    const float* xp = g_x + p;
    for (int c0 = 0; c0 < 256; c0 += 8) {
        float xv[8];
#pragma unroll
        for (int u = 0; u < 8; u++) xv[u] = xp[(size_t)(c0 + u) * HWP];
#pragma unroll
        for (int u = 0; u < 8; u++) {
            const float4* swr = (const float4*)sw[c0 + u];
#pragma unroll
            for (int t4 = 0; t4 < 11; t4++) {
                float4 w4 = swr[t4];
                acc[4 * t4 + 0] = fmaf(xv[u], w4.x, acc[4 * t4 + 0]);
                acc[4 * t4 + 1] = fmaf(xv[u], w4.y, acc[4 * t4 + 1]);
                acc[4 * t4 + 2] = fmaf(xv[u], w4.z, acc[4 * t4 + 2]);
                acc[4 * t4 + 3] = fmaf(xv[u], w4.w, acc[4 * t4 + 3]);
            }
            acc[44] = fmaf(xv[u], sw[c0 + u][44], acc[44]);
        }
    }
#pragma unroll
    for (int a = 0; a < 9; a++)  g_conf[(size_t)p * 9 + a] = acc[a];
#pragma unroll
    for (int t = 0; t < 36; t++) g_offs[(size_t)p * 36 + t] = acc[9 + t];
}

// ---------------- radix select (find 6000th-largest score bits) ----------------
__global__ void hist_kernel(int shift) {
    __shared__ unsigned h[256];
    if (threadIdx.x < 256) h[threadIdx.x] = 0;
    __syncthreads();
    unsigned msk = g_maskv, pfx = g_prefix;
    int stride = gridDim.x * blockDim.x;
    const float4* c4 = (const float4*)g_conf;
    for (int i = blockIdx.x * blockDim.x + threadIdx.x; i < NA / 4; i += stride) {
        float4 v = c4[i];
        unsigned a = ordf(v.x), b = ordf(v.y), cc = ordf(v.z), d = ordf(v.w);
        if ((a & msk) == pfx)  atomicAdd(&h[(a >> shift) & 255], 1);
        if ((b & msk) == pfx)  atomicAdd(&h[(b >> shift) & 255], 1);
        if ((cc & msk) == pfx) atomicAdd(&h[(cc >> shift) & 255], 1);
        if ((d & msk) == pfx)  atomicAdd(&h[(d >> shift) & 255], 1);
    }
    __syncthreads();
    if (threadIdx.x < 256 && h[threadIdx.x]) atomicAdd(&g_hist[threadIdx.x], h[threadIdx.x]);
}

__global__ void pick_kernel(int shift) {
    unsigned cum = 0; int k = g_k; int chosen = 0;
    for (int b = 255; b >= 0; b--) {
        unsigned c = g_hist[b];
        if (cum + c >= (unsigned)k) { chosen = b; break; }
        cum += c;
    }
    g_prefix |= ((unsigned)chosen) << shift;
    g_maskv  |= 0xFFu << shift;
    g_k = k - (int)cum;
    for (int i = 0; i < 256; i++) g_hist[i] = 0;
    if (shift == 0) g_thresh = g_prefix;
}

__global__ void gather_kernel() {
    unsigned T = g_thresh;
    int stride = gridDim.x * blockDim.x;
    const float4* c4 = (const float4*)g_conf;
    for (int i = blockIdx.x * blockDim.x + threadIdx.x; i < NA / 4; i += stride) {
        float4 v = c4[i];
        unsigned u[4] = {ordf(v.x), ordf(v.y), ordf(v.z), ordf(v.w)};
#pragma unroll
        for (int q = 0; q < 4; q++) {
            if (u[q] > T)       { int p = atomicAdd(&g_cntGT, 1); g_idxGT[p] = 4 * i + q; }
            else if (u[q] == T) { int p = atomicAdd(&g_cntEQ, 1); g_idxEQ[p] = 4 * i + q; }
        }
    }
}

// build unsorted candidate list; ties at threshold broken by lowest index
__global__ void __launch_bounds__(1024) finalize_kernel() {
    __shared__ unsigned s[8192];
    __shared__ unsigned redm[32];
    int tid = threadIdx.x; int nt = blockDim.x;
    int cGT = g_cntGT, cEQ = g_cntEQ;
    int need = PRE_NMS - cGT;
    for (int i = tid; i < cGT; i += nt) g_cand[i] = g_idxGT[i];
    if (need <= 0) return;
    if (cEQ <= 64) {
        if (tid == 0) {
            unsigned last = 0;
            for (int sel = 0; sel < need; sel++) {
                unsigned mn = 0xFFFFFFFFu;
                for (int i = 0; i < cEQ; i++) {
                    unsigned v = (unsigned)g_idxEQ[i];
                    if (v >= last && v < mn) mn = v;
                }
                g_cand[cGT + sel] = (int)mn;
                last = mn + 1;
            }
        }
        return;
    }
    if (cEQ <= 8192) {
        for (int i = tid; i < 8192; i += nt)
            s[i] = (i < cEQ) ? (unsigned)g_idxEQ[i] : 0xFFFFFFFFu;
        __syncthreads();
        for (int k = 2; k <= 8192; k <<= 1)
            for (int j = k >> 1; j > 0; j >>= 1) {
                for (int t2 = tid; t2 < 8192; t2 += nt) {
                    int ixj = t2 ^ j;
                    if (ixj > t2) {
                        unsigned a = s[t2], b = s[ixj];
                        if (((t2 & k) == 0) ? (a > b) : (a < b)) { s[t2] = b; s[ixj] = a; }
                    }
                }
                __syncthreads();
            }
        for (int i = tid; i < need; i += nt) g_cand[cGT + i] = (int)s[i];
    } else {
        unsigned last = 0;
        for (int sel = 0; sel < need; sel++) {
            unsigned mn = 0xFFFFFFFFu;
            for (int i = tid; i < cEQ; i += nt) {
                unsigned v = (unsigned)g_idxEQ[i];
                if (v >= last && v < mn) mn = v;
            }
            for (int o = 16; o > 0; o >>= 1) mn = min(mn, __shfl_down_sync(0xFFFFFFFFu, mn, o));
            if ((tid & 31) == 0) redm[tid >> 5] = mn;
            __syncthreads();
            if (tid == 0) {
                unsigned m = 0xFFFFFFFFu;
                for (int w = 0; w < nt / 32; w++) m = min(m, redm[w]);
                g_cand[cGT + sel] = (int)m;
                redm[0] = m;
            }
            __syncthreads();
            last = redm[0] + 1;
            __syncthreads();
        }
    }
}

// ---------------- sort 6000 candidates: descending score, ties ascending index ----------------
extern __shared__ unsigned long long skey[];
__global__ void __launch_bounds__(1024) sort_kernel() {
    int tid = threadIdx.x; int nt = blockDim.x;
    for (int i = tid; i < 8192; i += nt) {
        unsigned long long key = 0xFFFFFFFFFFFFFFFFull;
        if (i < PRE_NMS) {
            int idx = g_cand[i];
            unsigned v = ordf(g_conf[idx]);
            key = (((unsigned long long)(~v)) << 32) | (unsigned)idx;
        }
        skey[i] = key;
    }
    __syncthreads();
    for (int k = 2; k <= 8192; k <<= 1)
        for (int j = k >> 1; j > 0; j >>= 1) {
            for (int t2 = tid; t2 < 8192; t2 += nt) {
                int ixj = t2 ^ j;
                if (ixj > t2) {
                    unsigned long long a = skey[t2], b = skey[ixj];
                    if (((t2 & k) == 0) ? (a > b) : (a < b)) { skey[t2] = b; skey[ixj] = a; }
                }
            }
            __syncthreads();
        }
    for (int i = tid; i < PRE_NMS; i += nt)
        g_sortedIdx[i] = (int)(unsigned)(skey[i] & 0xFFFFFFFFull);
}

// ---------------- decode + clip + min-size filter ----------------
__global__ void decode_kernel(const int* __restrict__ imh, const int* __restrict__ imw) {
    int i = blockIdx.x * blockDim.x + threadIdx.x;
    if (i >= PRE_NMS) return;
    int idx = g_sortedIdx[i];
    int a = idx % 9; int p = idx / 9;
    int wc = p % FW, hr = p / FW;
    const double S[3] = {32.0, 64.0, 128.0};
    const double R[3] = {0.5, 1.0, 2.0};
    int si = a / 3, ri = a - si * 3;
    double wd = S[si] * sqrt(1.0 / R[ri]);
    double hd = S[si] * sqrt(R[ri]);
    float bx1 = (float)(-wd * 0.5), bx2 = (float)(wd * 0.5);
    float by1 = (float)(-hd * 0.5), by2 = (float)(hd * 0.5);
    float cx = ((float)wc + 0.5f) * 4.f, cy = ((float)hr + 0.5f) * 4.f;
    float ax1 = cx + bx1, ay1 = cy + by1, ax2 = cx + bx2, ay2 = cy + by2;
    float wa = ax2 - ax1, ha = ay2 - ay1;
    float cxa = ax1 + 0.5f * wa, cya = ay1 + 0.5f * ha;
    float d0 = g_offs[(size_t)idx * 4 + 0], d1 = g_offs[(size_t)idx * 4 + 1];
    float d2 = g_offs[(size_t)idx * 4 + 2], d3 = g_offs[(size_t)idx * 4 + 3];
    float pcx = d0 * wa + cxa, pcy = d1 * ha + cya;
    float pw = expf(d2) * wa, ph = expf(d3) * ha;
    float x1 = pcx - 0.5f * pw, y1 = pcy - 0.5f * ph;
    float x2 = pcx + 0.5f * pw, y2 = pcy + 0.5f * ph;
    float Wf = (float)imw[0], Hf = (float)imh[0];
    x1 = fminf(fmaxf(x1, 0.f), Wf); x2 = fminf(fmaxf(x2, 0.f), Wf);
    y1 = fminf(fmaxf(y1, 0.f), Hf); y2 = fminf(fmaxf(y2, 0.f), Hf);
    g_boxes[i] = make_float4(x1, y1, x2, y2);
    g_valid[i] = ((x2 - x1) >= 1.f) && ((y2 - y1) >= 1.f);
}

// ---------------- suppression bitmask (j < i with IoU > 0.7), 2D-tiled ----------------
#define JSEG 384
__global__ void __launch_bounds__(128) supmask_kernel() {
    __shared__ float4 tb[128];
    __shared__ float ta[128];
    int i = blockIdx.x * 128 + threadIdx.x;
    int seg0 = blockIdx.y * JSEG;
    if (seg0 >= (int)(blockIdx.x + 1) * 128) return;   // no j<i work in this segment
    bool act = i < PRE_NMS;
    float4 bi = make_float4(0, 0, 0, 0);
    float areai = 0.f;
    if (act) { bi = g_boxes[i]; areai = (bi.z - bi.x) * (bi.w - bi.y); }
    int segend = min(seg0 + JSEG, PRE_NMS);
    unsigned long long bits = 0;
    for (int t0 = seg0; t0 < segend; t0 += 128) {
        __syncthreads();
        int j0 = t0 + threadIdx.x;
        float4 bj0 = (j0 < PRE_NMS) ? g_boxes[j0] : make_float4(0, 0, 0, 0);
        tb[threadIdx.x] = bj0;
        ta[threadIdx.x] = (bj0.z - bj0.x) * (bj0.w - bj0.y);
        __syncthreads();
        if (act && t0 < i) {
            int jend = min(128, min(i, segend) - t0);
#pragma unroll 4
            for (int jj = 0; jj < jend; jj++) {
                int j = t0 + jj;
                float4 bj = tb[jj];
                float xx1 = fmaxf(bi.x, bj.x), yy1 = fmaxf(bi.y, bj.y);
                float xx2 = fminf(bi.z, bj.z), yy2 = fminf(bi.w, bj.w);
                float ww = fmaxf(xx2 - xx1, 0.f), hh = fmaxf(yy2 - yy1, 0.f);
                float inter = ww * hh;
                if (inter > 0.f) {
                    float iou = inter / (areai + ta[jj] - inter + 1e-9f);
                    if (iou > 0.7f) bits |= 1ULL << (j & 63);
                }
                if ((j & 63) == 63) { g_sup[(size_t)i * MWORDS + (j >> 6)] = bits; bits = 0; }
            }
        }
    }
    if (act) {
        int jl = min(i, segend);
        if (jl > seg0 && (jl & 63)) g_sup[(size_t)i * MWORDS + ((jl - 1) >> 6)] = bits;
    }
}

// ---------------- greedy NMS scan, block-64 two-phase (single warp) ----------------
__global__ void nms_scan_kernel(float* __restrict__ out) {
    __shared__ unsigned long long kept[MWORDS];
    __shared__ unsigned long long rowb[64];
    int lane = threadIdx.x;
    for (int w = lane; w < MWORDS; w += 32) kept[w] = 0;
    __syncwarp();
    int cnt = 0;
    for (int b = 0; b < MWORDS; b++) {
        int base = b * 64;
        int i0 = base + lane;
        int i1 = base + lane + 32;
        bool h0 = true, h1 = true;
        const unsigned long long* r0 = g_sup + (size_t)i0 * MWORDS;
        const unsigned long long* r1 = g_sup + (size_t)i1 * MWORDS;
        if (i0 < PRE_NMS) { h0 = !g_valid[i0]; rowb[lane] = r0[b]; }
        if (i1 < PRE_NMS) { h1 = !g_valid[i1]; rowb[lane + 32] = r1[b]; }
#pragma unroll 4
        for (int w = 0; w < b; w++) {
            unsigned long long kw = kept[w];
            if (i0 < PRE_NMS) h0 |= (r0[w] & kw) != 0ull;
            if (i1 < PRE_NMS) h1 |= (r1[w] & kw) != 0ull;
        }
        unsigned m0 = __ballot_sync(0xFFFFFFFFu, h0);
        unsigned m1 = __ballot_sync(0xFFFFFFFFu, h1);
        unsigned long long hitg = (((unsigned long long)m1) << 32) | (unsigned long long)m0;
        __syncwarp();
        if (lane == 0) {
            unsigned long long todo = ~hitg;
            unsigned long long local = 0;
            while (todo) {
                int i = __ffsll((long long)todo) - 1;
                todo &= todo - 1;
                if (!(rowb[i] & local)) {
                    local |= 1ull << i;
                    if (cnt < POST_NMS) ((float4*)out)[cnt] = g_boxes[base + i];
                    cnt++;
                    if (cnt >= POST_NMS) break;
                }
            }
            kept[b] = local;
        }
        cnt = __shfl_sync(0xFFFFFFFFu, cnt, 0);
        if (cnt >= POST_NMS) break;
        __syncwarp();
    }
}

// ---------------- launch ----------------
extern "C" void kernel_launch(void* const* d_in, const int* in_sizes, int n_in,
                              void* d_out, int out_size) {
    const float* feature = (const float*)d_in[0];
    const float* w1   = (const float*)d_in[1];
    const float* b1   = (const float*)d_in[2];
    const float* wcls = (const float*)d_in[3];
    const float* bcls = (const float*)d_in[4];
    const float* wreg = (const float*)d_in[5];
    const float* breg = (const float*)d_in[6];
    const int* imh = (const int*)d_in[7];
    const int* imw = (const int*)d_in[8];
    float* out = (float*)d_out;

    cudaFuncSetAttribute(sort_kernel, cudaFuncAttributeMaxDynamicSharedMemorySize, 8192 * 8);
    cudaFuncSetAttribute(conv3x3_kernel, cudaFuncAttributeMaxDynamicSharedMemorySize, SM_TOTALB);

    init_kernel<<<16, 256>>>(out, out_size);
    wtrans_kernel<<<(CIN * CIN * 9 + 255) / 256, 256>>>(w1);
    conv3x3_kernel<<<dim3(FW / 16, FH / 8, CIN / 64), 128, SM_TOTALB>>>(feature, b1);
    heads_kernel<<<(HWP + 127) / 128, 128>>>(wcls, bcls, wreg, breg);
    for (int pass = 3; pass >= 0; pass--) {
        hist_kernel<<<480, 256>>>(pass * 8);
        pick_kernel<<<1, 1>>>(pass * 8);
    }
    gather_kernel<<<480, 256>>>();
    finalize_kernel<<<1, 1024>>>();
    sort_kernel<<<1, 1024, 8192 * 8>>>();
    decode_kernel<<<(PRE_NMS + 127) / 128, 128>>>(imh, imw);
    supmask_kernel<<<dim3((PRE_NMS + 127) / 128, 16), 128>>>();
    nms_scan_kernel<<<1, 32>>>(out);
}

// round 15
// speedup vs baseline: 1.0858x; 1.0858x over previous
#include <cuda_runtime.h>
#include <math.h>
#include <stdint.h>

// ---------------- problem constants ----------------
#define FH 200
#define FW 272
#define HWP (FH*FW)          // 54400 pixels
#define CIN 256
#define NA (HWP*9)           // 489600 anchors
#define PRE_NMS 6000
#define POST_NMS 1000
#define MWORDS 94            // ceil(6000/64)

// ---------------- device scratch (static, no allocs) ----------------
__device__ float g_x[CIN*HWP];                    // conv1 output (relu'd), NCHW
__device__ float g_wT[CIN*9*256];                 // transposed weights [ci][k][co]
__device__ float g_conf[NA];
__device__ float g_offs[NA*4];
__device__ int   g_idxGT[PRE_NMS];
__device__ int   g_idxEQ[NA];
__device__ int   g_cand[PRE_NMS];
__device__ int   g_sortedIdx[PRE_NMS];
__device__ float4 g_boxes[PRE_NMS];
__device__ unsigned char g_valid[PRE_NMS];
__device__ unsigned long long g_sup[(size_t)PRE_NMS*MWORDS + 1024];

__device__ unsigned g_hist[256];
__device__ unsigned g_prefix, g_maskv, g_thresh;
__device__ int g_k, g_cntGT, g_cntEQ;

// ---------------- helpers ----------------
__device__ __forceinline__ unsigned ordf(float f) {
    unsigned u = __float_as_uint(f);
    return (u & 0x80000000u) ? ~u : (u | 0x80000000u);   // monotonic increasing map
}
__device__ __forceinline__ unsigned long long fma2(unsigned long long a,
                                                   unsigned long long b,
                                                   unsigned long long c) {
    unsigned long long d;
    asm("fma.rn.f32x2 %0, %1, %2, %3;" : "=l"(d) : "l"(a), "l"(b), "l"(c));
    return d;
}
__device__ __forceinline__ unsigned long long pack2(float x, float y) {
    unsigned long long r;
    asm("mov.b64 %0, {%1, %2};" : "=l"(r) : "f"(x), "f"(y));
    return r;
}
__device__ __forceinline__ float2 unpack2(unsigned long long v) {
    float2 r;
    asm("mov.b64 {%0, %1}, %2;" : "=f"(r.x), "=f"(r.y) : "l"(v));
    return r;
}
__device__ __forceinline__ void cpa16(uint32_t dst, const void* src) {
    asm volatile("cp.async.cg.shared.global [%0], [%1], 16;" :: "r"(dst), "l"(src));
}
__device__ __forceinline__ void cpa4(uint32_t dst, const void* src, bool p) {
    int sz = p ? 4 : 0;
    asm volatile("cp.async.ca.shared.global [%0], [%1], 4, %2;" :: "r"(dst), "l"(src), "r"(sz));
}
__device__ __forceinline__ void cpa_commit() { asm volatile("cp.async.commit_group;"); }
__device__ __forceinline__ void cpa_wait1()  { asm volatile("cp.async.wait_group 1;"); }
__device__ __forceinline__ void cpa_wait0()  { asm volatile("cp.async.wait_group 0;"); }

// ---------------- init ----------------
__global__ void init_kernel(float* out, int out_n) {
    int t = blockIdx.x * blockDim.x + threadIdx.x;
    for (int i = t; i < out_n; i += gridDim.x * blockDim.x) out[i] = 0.f;
    if (blockIdx.x == 0) {
        if (threadIdx.x < 256) g_hist[threadIdx.x] = 0;
        if (threadIdx.x == 0) {
            g_prefix = 0; g_maskv = 0; g_k = PRE_NMS;
            g_cntGT = 0; g_cntEQ = 0;
        }
    }
}

// ---------------- weight transpose: w1[co][ci][k] -> wT[ci][k][co] ----------------
__global__ void wtrans_kernel(const float* __restrict__ w1) {
    int t = blockIdx.x * blockDim.x + threadIdx.x;
    if (t >= CIN * CIN * 9) return;
    int co = t & 255;
    int rem = t >> 8;          // ci*9 + k
    int k = rem % 9;
    int ci = rem / 9;
    g_wT[(size_t)rem * 256 + co] = w1[(co * CIN + ci) * 9 + k];
}

// ---------------- conv 3x3 + relu (co-paired f32x2, cp.async double-buffered) ----------------
// R13 config (proven): 128 threads, 8 px x 4 co-pairs/thread; ci loop unroll 2 for ILP.
#define SW_ELEMS 9216
#define SM_TOTALB ((SW_ELEMS + 3200) * 4)
__global__ void __launch_bounds__(128, 3) conv3x3_kernel(const float* __restrict__ f,
                                                         const float* __restrict__ b1) {
    extern __shared__ float sm[];
    uint32_t sbase;
    asm("{ .reg .u64 t; cvta.to.shared.u64 t, %1; cvt.u32.u64 %0, t; }"
        : "=r"(sbase) : "l"(sm));

    const int tid = threadIdx.x;
    const int cot = tid & 7;           // co-pair group: pairs cot + 8*o, o=0..3
    const int pt  = tid >> 3;          // 0..15 pixel groups
    const int pr  = pt >> 1;           // row 0..7
    const int pc  = (pt & 1) << 3;     // col base 0 or 8
    const int tileC = blockIdx.x * 16;
    const int tileR = blockIdx.y * 8;
    const int co0   = blockIdx.z * 64;

    unsigned long long acc[4][8];      // [co-pair o][pixel j]
#pragma unroll
    for (int o = 0; o < 4; o++)
#pragma unroll
        for (int j = 0; j < 8; j++) acc[o][j] = 0ull;

    auto stage = [&](int c, int b) {
        int ci0 = c * 8;
        const float* wsrc0 = g_wT + (size_t)(ci0 * 9) * 256 + co0;
        uint32_t wdst0 = sbase + (uint32_t)(b * 4608) * 4;
#pragma unroll
        for (int it = 0; it < 9; it++) {
            int g = tid + it * 128;            // 0..1151
            int row = g >> 4, gi = g & 15;
            cpa16(wdst0 + (uint32_t)(row * 64 + gi * 4) * 4,
                  wsrc0 + (size_t)row * 256 + gi * 4);
        }
        uint32_t idst0 = sbase + (uint32_t)(SW_ELEMS + b * 1600) * 4;
#pragma unroll
        for (int it = 0; it < 12; it++) {
            int e = tid + it * 128;
            if (e < 1440) {
                int ci = e / 180; int rem = e - ci * 180;
                int rr = rem / 18; int cc = rem - rr * 18;
                int gr = tileR + rr - 1, gc = tileC + cc - 1;
                bool ok = ((unsigned)gr < (unsigned)FH) & ((unsigned)gc < (unsigned)FW);
                cpa4(idst0 + (uint32_t)((ci * 10 + rr) * 20 + cc) * 4,
                     f + (size_t)(ci0 + ci) * HWP + gr * FW + gc, ok);
            }
        }
    };

    stage(0, 0);
    cpa_commit();

    for (int c = 0; c < 32; c++) {
        int b = c & 1;
        if (c < 31) { stage(c + 1, b ^ 1); cpa_commit(); cpa_wait1(); }
        else cpa_wait0();
        __syncthreads();

        const float* sW  = sm + b * 4608;
        const float* sIn = sm + SW_ELEMS + b * 1600;
#pragma unroll 2
        for (int ci = 0; ci < 8; ci++) {
#pragma unroll
            for (int dy = 0; dy < 3; dy++) {
                const float* r = sIn + (ci * 10 + pr + dy) * 20 + pc;
                float4 q0 = *(const float4*)r;
                float4 q1 = *(const float4*)(r + 4);
                float2 q2 = *(const float2*)(r + 8);
                unsigned long long X[10];
                X[0] = pack2(q0.x, q0.x); X[1] = pack2(q0.y, q0.y);
                X[2] = pack2(q0.z, q0.z); X[3] = pack2(q0.w, q0.w);
                X[4] = pack2(q1.x, q1.x); X[5] = pack2(q1.y, q1.y);
                X[6] = pack2(q1.z, q1.z); X[7] = pack2(q1.w, q1.w);
                X[8] = pack2(q2.x, q2.x); X[9] = pack2(q2.y, q2.y);
#pragma unroll
                for (int dx = 0; dx < 3; dx++) {
                    const float* wrow = sW + (ci * 9 + dy * 3 + dx) * 64 + 2 * cot;
#pragma unroll
                    for (int o = 0; o < 4; o++) {
                        unsigned long long w2 = *(const unsigned long long*)&wrow[16 * o];
#pragma unroll
                        for (int j = 0; j < 8; j++)
                            acc[o][j] = fma2(X[j + dx], w2, acc[o][j]);
                    }
                }
            }
        }
        __syncthreads();
    }

    const int gr = tileR + pr;
#pragma unroll
    for (int o = 0; o < 4; o++) {
        int coe = co0 + 2 * (cot + 8 * o);          // even co of the pair
        float be = b1[coe], bo = b1[coe + 1];
        float2 v[8];
#pragma unroll
        for (int j = 0; j < 8; j++) v[j] = unpack2(acc[o][j]);
        float4 ea, eb, oa, ob;
        ea.x = fmaxf(v[0].x + be, 0.f); ea.y = fmaxf(v[1].x + be, 0.f);
        ea.z = fmaxf(v[2].x + be, 0.f); ea.w = fmaxf(v[3].x + be, 0.f);
        eb.x = fmaxf(v[4].x + be, 0.f); eb.y = fmaxf(v[5].x + be, 0.f);
        eb.z = fmaxf(v[6].x + be, 0.f); eb.w = fmaxf(v[7].x + be, 0.f);
        oa.x = fmaxf(v[0].y + bo, 0.f); oa.y = fmaxf(v[1].y + bo, 0.f);
        oa.z = fmaxf(v[2].y + bo, 0.f); oa.w = fmaxf(v[3].y + bo, 0.f);
        ob.x = fmaxf(v[4].y + bo, 0.f); ob.y = fmaxf(v[5].y + bo, 0.f);
        ob.z = fmaxf(v[6].y + bo, 0.f); ob.w = fmaxf(v[7].y + bo, 0.f);
        float* de = &g_x[(size_t)coe * HWP + gr * FW + tileC + pc];
        float* dd = &g_x[(size_t)(coe + 1) * HWP + gr * FW + tileC + pc];
        *(float4*)de = ea; *(float4*)(de + 4) = eb;
        *(float4*)dd = oa; *(float4*)(dd + 4) = ob;
    }
}

// ---------------- 1x1 heads: conf (9) + offsets (36) ----------------
// 128-thread blocks, grid=425; c-batch of 16 for MLP (same ascending-c order).
__global__ void __launch_bounds__(128) heads_kernel(const float* __restrict__ wcls,
                                                    const float* __restrict__ bcls,
                                                    const float* __restrict__ wreg,
                                                    const float* __restrict__ breg) {
    __shared__ float sw[256][48];
    int tid = threadIdx.x;
    for (int idx = tid; idx < 256 * 45; idx += 128) {
        int c = idx / 45, t = idx - c * 45;
        sw[c][t] = (t < 9) ? wcls[t * 256 + c] : wreg[(t - 9) * 256 + c];
    }
    __syncthreads();
    int p = blockIdx.x * 128 + tid;
    if (p >= HWP) return;
    float acc[45];
#pragma unroll
    for (int t = 0; t < 9; t++)  acc[t] = bcls[t];
#pragma unroll
    for (int t = 0; t < 36; t++) acc[9 + t] = breg[t];
    const float* xp = g_x + p;
    for (int c0 = 0; c0 < 256; c0 += 16) {
        float xv[16];
#pragma unroll
        for (int u = 0; u < 16; u++) xv[u] = xp[(size_t)(c0 + u) * HWP];
#pragma unroll
        for (int u = 0; u < 16; u++) {
            const float4* swr = (const float4*)sw[c0 + u];
#pragma unroll
            for (int t4 = 0; t4 < 11; t4++) {
                float4 w4 = swr[t4];
                acc[4 * t4 + 0] = fmaf(xv[u], w4.x, acc[4 * t4 + 0]);
                acc[4 * t4 + 1] = fmaf(xv[u], w4.y, acc[4 * t4 + 1]);
                acc[4 * t4 + 2] = fmaf(xv[u], w4.z, acc[4 * t4 + 2]);
                acc[4 * t4 + 3] = fmaf(xv[u], w4.w, acc[4 * t4 + 3]);
            }
            acc[44] = fmaf(xv[u], sw[c0 + u][44], acc[44]);
        }
    }
#pragma unroll
    for (int a = 0; a < 9; a++)  g_conf[(size_t)p * 9 + a] = acc[a];
#pragma unroll
    for (int t = 0; t < 36; t++) g_offs[(size_t)p * 36 + t] = acc[9 + t];
}

// ---------------- radix select (find 6000th-largest score bits) ----------------
__global__ void hist_kernel(int shift) {
    __shared__ unsigned h[256];
    if (threadIdx.x < 256) h[threadIdx.x] = 0;
    __syncthreads();
    unsigned msk = g_maskv, pfx = g_prefix;
    int stride = gridDim.x * blockDim.x;
    const float4* c4 = (const float4*)g_conf;
    for (int i = blockIdx.x * blockDim.x + threadIdx.x; i < NA / 4; i += stride) {
        float4 v = c4[i];
        unsigned a = ordf(v.x), b = ordf(v.y), cc = ordf(v.z), d = ordf(v.w);
        if ((a & msk) == pfx)  atomicAdd(&h[(a >> shift) & 255], 1);
        if ((b & msk) == pfx)  atomicAdd(&h[(b >> shift) & 255], 1);
        if ((cc & msk) == pfx) atomicAdd(&h[(cc >> shift) & 255], 1);
        if ((d & msk) == pfx)  atomicAdd(&h[(d >> shift) & 255], 1);
    }
    __syncthreads();
    if (threadIdx.x < 256 && h[threadIdx.x]) atomicAdd(&g_hist[threadIdx.x], h[threadIdx.x]);
}

__global__ void pick_kernel(int shift) {
    unsigned cum = 0; int k = g_k; int chosen = 0;
    for (int b = 255; b >= 0; b--) {
        unsigned c = g_hist[b];
        if (cum + c >= (unsigned)k) { chosen = b; break; }
        cum += c;
    }
    g_prefix |= ((unsigned)chosen) << shift;
    g_maskv  |= 0xFFu << shift;
    g_k = k - (int)cum;
    for (int i = 0; i < 256; i++) g_hist[i] = 0;
    if (shift == 0) g_thresh = g_prefix;
}

__global__ void gather_kernel() {
    unsigned T = g_thresh;
    int stride = gridDim.x * blockDim.x;
    const float4* c4 = (const float4*)g_conf;
    for (int i = blockIdx.x * blockDim.x + threadIdx.x; i < NA / 4; i += stride) {
        float4 v = c4[i];
        unsigned u[4] = {ordf(v.x), ordf(v.y), ordf(v.z), ordf(v.w)};
#pragma unroll
        for (int q = 0; q < 4; q++) {
            if (u[q] > T)       { int p = atomicAdd(&g_cntGT, 1); g_idxGT[p] = 4 * i + q; }
            else if (u[q] == T) { int p = atomicAdd(&g_cntEQ, 1); g_idxEQ[p] = 4 * i + q; }
        }
    }
}

// build unsorted candidate list; ties at threshold broken by lowest index
__global__ void __launch_bounds__(1024) finalize_kernel() {
    __shared__ unsigned s[8192];
    __shared__ unsigned redm[32];
    int tid = threadIdx.x; int nt = blockDim.x;
    int cGT = g_cntGT, cEQ = g_cntEQ;
    int need = PRE_NMS - cGT;
    for (int i = tid; i < cGT; i += nt) g_cand[i] = g_idxGT[i];
    if (need <= 0) return;
    if (cEQ <= 64) {
        if (tid == 0) {
            unsigned last = 0;
            for (int sel = 0; sel < need; sel++) {
                unsigned mn = 0xFFFFFFFFu;
                for (int i = 0; i < cEQ; i++) {
                    unsigned v = (unsigned)g_idxEQ[i];
                    if (v >= last && v < mn) mn = v;
                }
                g_cand[cGT + sel] = (int)mn;
                last = mn + 1;
            }
        }
        return;
    }
    if (cEQ <= 8192) {
        for (int i = tid; i < 8192; i += nt)
            s[i] = (i < cEQ) ? (unsigned)g_idxEQ[i] : 0xFFFFFFFFu;
        __syncthreads();
        for (int k = 2; k <= 8192; k <<= 1)
            for (int j = k >> 1; j > 0; j >>= 1) {
                for (int t2 = tid; t2 < 8192; t2 += nt) {
                    int ixj = t2 ^ j;
                    if (ixj > t2) {
                        unsigned a = s[t2], b = s[ixj];
                        if (((t2 & k) == 0) ? (a > b) : (a < b)) { s[t2] = b; s[ixj] = a; }
                    }
                }
                __syncthreads();
            }
        for (int i = tid; i < need; i += nt) g_cand[cGT + i] = (int)s[i];
    } else {
        unsigned last = 0;
        for (int sel = 0; sel < need; sel++) {
            unsigned mn = 0xFFFFFFFFu;
            for (int i = tid; i < cEQ; i += nt) {
                unsigned v = (unsigned)g_idxEQ[i];
                if (v >= last && v < mn) mn = v;
            }
            for (int o = 16; o > 0; o >>= 1) mn = min(mn, __shfl_down_sync(0xFFFFFFFFu, mn, o));
            if ((tid & 31) == 0) redm[tid >> 5] = mn;
            __syncthreads();
            if (tid == 0) {
                unsigned m = 0xFFFFFFFFu;
                for (int w = 0; w < nt / 32; w++) m = min(m, redm[w]);
                g_cand[cGT + sel] = (int)m;
                redm[0] = m;
            }
            __syncthreads();
            last = redm[0] + 1;
            __syncthreads();
        }
    }
}

// ---------------- sort 6000 candidates: descending score, ties ascending index ----------------
extern __shared__ unsigned long long skey[];
__global__ void __launch_bounds__(1024) sort_kernel() {
    int tid = threadIdx.x; int nt = blockDim.x;
    for (int i = tid; i < 8192; i += nt) {
        unsigned long long key = 0xFFFFFFFFFFFFFFFFull;
        if (i < PRE_NMS) {
            int idx = g_cand[i];
            unsigned v = ordf(g_conf[idx]);
            key = (((unsigned long long)(~v)) << 32) | (unsigned)idx;
        }
        skey[i] = key;
    }
    __syncthreads();
    for (int k = 2; k <= 8192; k <<= 1)
        for (int j = k >> 1; j > 0; j >>= 1) {
            for (int t2 = tid; t2 < 8192; t2 += nt) {
                int ixj = t2 ^ j;
                if (ixj > t2) {
                    unsigned long long a = skey[t2], b = skey[ixj];
                    if (((t2 & k) == 0) ? (a > b) : (a < b)) { skey[t2] = b; skey[ixj] = a; }
                }
            }
            __syncthreads();
        }
    for (int i = tid; i < PRE_NMS; i += nt)
        g_sortedIdx[i] = (int)(unsigned)(skey[i] & 0xFFFFFFFFull);
}

// ---------------- decode + clip + min-size filter ----------------
__global__ void decode_kernel(const int* __restrict__ imh, const int* __restrict__ imw) {
    int i = blockIdx.x * blockDim.x + threadIdx.x;
    if (i >= PRE_NMS) return;
    int idx = g_sortedIdx[i];
    int a = idx % 9; int p = idx / 9;
    int wc = p % FW, hr = p / FW;
    const double S[3] = {32.0, 64.0, 128.0};
    const double R[3] = {0.5, 1.0, 2.0};
    int si = a / 3, ri = a - si * 3;
    double wd = S[si] * sqrt(1.0 / R[ri]);
    double hd = S[si] * sqrt(R[ri]);
    float bx1 = (float)(-wd * 0.5), bx2 = (float)(wd * 0.5);
    float by1 = (float)(-hd * 0.5), by2 = (float)(hd * 0.5);
    float cx = ((float)wc + 0.5f) * 4.f, cy = ((float)hr + 0.5f) * 4.f;
    float ax1 = cx + bx1, ay1 = cy + by1, ax2 = cx + bx2, ay2 = cy + by2;
    float wa = ax2 - ax1, ha = ay2 - ay1;
    float cxa = ax1 + 0.5f * wa, cya = ay1 + 0.5f * ha;
    float d0 = g_offs[(size_t)idx * 4 + 0], d1 = g_offs[(size_t)idx * 4 + 1];
    float d2 = g_offs[(size_t)idx * 4 + 2], d3 = g_offs[(size_t)idx * 4 + 3];
    float pcx = d0 * wa + cxa, pcy = d1 * ha + cya;
    float pw = expf(d2) * wa, ph = expf(d3) * ha;
    float x1 = pcx - 0.5f * pw, y1 = pcy - 0.5f * ph;
    float x2 = pcx + 0.5f * pw, y2 = pcy + 0.5f * ph;
    float Wf = (float)imw[0], Hf = (float)imh[0];
    x1 = fminf(fmaxf(x1, 0.f), Wf); x2 = fminf(fmaxf(x2, 0.f), Wf);
    y1 = fminf(fmaxf(y1, 0.f), Hf); y2 = fminf(fmaxf(y2, 0.f), Hf);
    g_boxes[i] = make_float4(x1, y1, x2, y2);
    g_valid[i] = ((x2 - x1) >= 1.f) && ((y2 - y1) >= 1.f);
}

// ---------------- suppression bitmask (j < i with IoU > 0.7), 2D-tiled ----------------
#define JSEG 384
__global__ void __launch_bounds__(128) supmask_kernel() {
    __shared__ float4 tb[128];
    __shared__ float ta[128];
    int i = blockIdx.x * 128 + threadIdx.x;
    int seg0 = blockIdx.y * JSEG;
    if (seg0 >= (int)(blockIdx.x + 1) * 128) return;   // no j<i work in this segment
    bool act = i < PRE_NMS;
    float4 bi = make_float4(0, 0, 0, 0);
    float areai = 0.f;
    if (act) { bi = g_boxes[i]; areai = (bi.z - bi.x) * (bi.w - bi.y); }
    int segend = min(seg0 + JSEG, PRE_NMS);
    unsigned long long bits = 0;
    for (int t0 = seg0; t0 < segend; t0 += 128) {
        __syncthreads();
        int j0 = t0 + threadIdx.x;
        float4 bj0 = (j0 < PRE_NMS) ? g_boxes[j0] : make_float4(0, 0, 0, 0);
        tb[threadIdx.x] = bj0;
        ta[threadIdx.x] = (bj0.z - bj0.x) * (bj0.w - bj0.y);
        __syncthreads();
        if (act && t0 < i) {
            int jend = min(128, min(i, segend) - t0);
#pragma unroll 4
            for (int jj = 0; jj < jend; jj++) {
                int j = t0 + jj;
                float4 bj = tb[jj];
                float xx1 = fmaxf(bi.x, bj.x), yy1 = fmaxf(bi.y, bj.y);
                float xx2 = fminf(bi.z, bj.z), yy2 = fminf(bi.w, bj.w);
                float ww = fmaxf(xx2 - xx1, 0.f), hh = fmaxf(yy2 - yy1, 0.f);
                float inter = ww * hh;
                if (inter > 0.f) {
                    float iou = inter / (areai + ta[jj] - inter + 1e-9f);
                    if (iou > 0.7f) bits |= 1ULL << (j & 63);
                }
                if ((j & 63) == 63) { g_sup[(size_t)i * MWORDS + (j >> 6)] = bits; bits = 0; }
            }
        }
    }
    if (act) {
        int jl = min(i, segend);
        if (jl > seg0 && (jl & 63)) g_sup[(size_t)i * MWORDS + ((jl - 1) >> 6)] = bits;
    }
}

// ---------------- greedy NMS scan, block-64 two-phase (single warp) ----------------
__global__ void nms_scan_kernel(float* __restrict__ out) {
    __shared__ unsigned long long kept[MWORDS];
    __shared__ unsigned long long rowb[64];
    int lane = threadIdx.x;
    for (int w = lane; w < MWORDS; w += 32) kept[w] = 0;
    __syncwarp();
    int cnt = 0;
    for (int b = 0; b < MWORDS; b++) {
        int base = b * 64;
        int i0 = base + lane;
        int i1 = base + lane + 32;
        bool h0 = true, h1 = true;
        const unsigned long long* r0 = g_sup + (size_t)i0 * MWORDS;
        const unsigned long long* r1 = g_sup + (size_t)i1 * MWORDS;
        if (i0 < PRE_NMS) { h0 = !g_valid[i0]; rowb[lane] = r0[b]; }
        if (i1 < PRE_NMS) { h1 = !g_valid[i1]; rowb[lane + 32] = r1[b]; }
#pragma unroll 4
        for (int w = 0; w < b; w++) {
            unsigned long long kw = kept[w];
            if (i0 < PRE_NMS) h0 |= (r0[w] & kw) != 0ull;
            if (i1 < PRE_NMS) h1 |= (r1[w] & kw) != 0ull;
        }
        unsigned m0 = __ballot_sync(0xFFFFFFFFu, h0);
        unsigned m1 = __ballot_sync(0xFFFFFFFFu, h1);
        unsigned long long hitg = (((unsigned long long)m1) << 32) | (unsigned long long)m0;
        __syncwarp();
        if (lane == 0) {
            unsigned long long todo = ~hitg;
            unsigned long long local = 0;
            while (todo) {
                int i = __ffsll((long long)todo) - 1;
                todo &= todo - 1;
                if (!(rowb[i] & local)) {
                    local |= 1ull << i;
                    if (cnt < POST_NMS) ((float4*)out)[cnt] = g_boxes[base + i];
                    cnt++;
                    if (cnt >= POST_NMS) break;
                }
            }
            kept[b] = local;
        }
        cnt = __shfl_sync(0xFFFFFFFFu, cnt, 0);
        if (cnt >= POST_NMS) break;
        __syncwarp();
    }
}

// ---------------- launch ----------------
extern "C" void kernel_launch(void* const* d_in, const int* in_sizes, int n_in,
                              void* d_out, int out_size) {
    const float* feature = (const float*)d_in[0];
    const float* w1   = (const float*)d_in[1];
    const float* b1   = (const float*)d_in[2];
    const float* wcls = (const float*)d_in[3];
    const float* bcls = (const float*)d_in[4];
    const float* wreg = (const float*)d_in[5];
    const float* breg = (const float*)d_in[6];
    const int* imh = (const int*)d_in[7];
    const int* imw = (const int*)d_in[8];
    float* out = (float*)d_out;

    cudaFuncSetAttribute(sort_kernel, cudaFuncAttributeMaxDynamicSharedMemorySize, 8192 * 8);
    cudaFuncSetAttribute(conv3x3_kernel, cudaFuncAttributeMaxDynamicSharedMemorySize, SM_TOTALB);

    init_kernel<<<16, 256>>>(out, out_size);
    wtrans_kernel<<<(CIN * CIN * 9 + 255) / 256, 256>>>(w1);
    conv3x3_kernel<<<dim3(FW / 16, FH / 8, CIN / 64), 128, SM_TOTALB>>>(feature, b1);
    heads_kernel<<<(HWP + 127) / 128, 128>>>(wcls, bcls, wreg, breg);
    for (int pass = 3; pass >= 0; pass--) {
        hist_kernel<<<480, 256>>>(pass * 8);
        pick_kernel<<<1, 1>>>(pass * 8);
    }
    gather_kernel<<<480, 256>>>();
    finalize_kernel<<<1, 1024>>>();
    sort_kernel<<<1, 1024, 8192 * 8>>>();
    decode_kernel<<<(PRE_NMS + 127) / 128, 128>>>(imh, imw);
    supmask_kernel<<<dim3((PRE_NMS + 127) / 128, 16), 128>>>();
    nms_scan_kernel<<<1, 32>>>(out);
}